// round 4
// baseline (speedup 1.0000x reference)
#include <cuda_runtime.h>
#include <math.h>
#include <stdint.h>

// Problem constants
#define BB 2
#define TT 2048
#define HH 16
#define DD 64
#define CC 1024

// Scratch (device globals: allocation-free per harness rules)
__device__ float g_qkv[BB * TT * 3 * CC];
__device__ float g_q[BB * HH * TT * DD];
__device__ float g_k[BB * HH * TT * DD];
__device__ float g_v[BB * HH * TT * DD];
__device__ float g_y[BB * TT * CC];

// ---------------------------------------------------------------------------
// tf32 / async helpers
// ---------------------------------------------------------------------------
__device__ __forceinline__ unsigned tf32u(float x) {
    unsigned u;
    asm("cvt.rna.tf32.f32 %0, %1;" : "=r"(u) : "f"(x));
    return u;
}
__device__ __forceinline__ float tf32f(float x) {
    return __uint_as_float(tf32u(x));
}

__device__ __forceinline__ void mma_tf32(float* d,
    unsigned a0, unsigned a1, unsigned a2, unsigned a3,
    unsigned b0, unsigned b1)
{
    asm volatile(
        "mma.sync.aligned.m16n8k8.row.col.f32.tf32.tf32.f32 "
        "{%0,%1,%2,%3}, {%4,%5,%6,%7}, {%8,%9}, {%0,%1,%2,%3};\n"
        : "+f"(d[0]), "+f"(d[1]), "+f"(d[2]), "+f"(d[3])
        : "r"(a0), "r"(a1), "r"(a2), "r"(a3), "r"(b0), "r"(b1));
}

__device__ __forceinline__ void cp16(uint32_t s, const void* g) {
    asm volatile("cp.async.cg.shared.global [%0], [%1], 16;\n" :: "r"(s), "l"(g));
}

// ---------------------------------------------------------------------------
// tf32 tensor-core GEMM: C[m][n] = sum_k A[m][k] * B[n][k]  (C = A * B^T)
// 128x128 block tile, BK=32, 256 threads (8 warps), warp tile 64x32.
// ---------------------------------------------------------------------------
#define GP 36

__global__ __launch_bounds__(256) void mma_gemm_abt(
    const float* __restrict__ A, const float* __restrict__ Bm,
    float* __restrict__ Cm, int M, int N, int K)
{
    __shared__ __align__(16) unsigned As[128 * GP];
    __shared__ __align__(16) unsigned Bs[128 * GP];

    const int tid  = threadIdx.x;
    const int warp = tid >> 5;
    const int lane = tid & 31;
    const int g = lane >> 2;
    const int c = lane & 3;

    const int wm = (warp & 1) * 64;
    const int wn = (warp >> 1) * 32;

    const int bm = blockIdx.y * 128;
    const int bn = blockIdx.x * 128;

    const int lrow = tid >> 3;
    const int lcol = (tid & 7) * 4;

    float acc[4][4][4];
#pragma unroll
    for (int i = 0; i < 4; i++)
#pragma unroll
        for (int j = 0; j < 4; j++)
#pragma unroll
            for (int r = 0; r < 4; r++) acc[i][j][r] = 0.0f;

    for (int k0 = 0; k0 < K; k0 += 32) {
        float4 va[4], vb[4];
#pragma unroll
        for (int i = 0; i < 4; i++) {
            va[i] = *(const float4*)(A + (size_t)(bm + lrow + i * 32) * K + k0 + lcol);
            vb[i] = *(const float4*)(Bm + (size_t)(bn + lrow + i * 32) * K + k0 + lcol);
        }
        __syncthreads();
#pragma unroll
        for (int i = 0; i < 4; i++) {
            unsigned* ap = &As[(lrow + i * 32) * GP + lcol];
            ap[0] = tf32u(va[i].x); ap[1] = tf32u(va[i].y);
            ap[2] = tf32u(va[i].z); ap[3] = tf32u(va[i].w);
            unsigned* bp = &Bs[(lrow + i * 32) * GP + lcol];
            bp[0] = tf32u(vb[i].x); bp[1] = tf32u(vb[i].y);
            bp[2] = tf32u(vb[i].z); bp[3] = tf32u(vb[i].w);
        }
        __syncthreads();

#pragma unroll
        for (int ks = 0; ks < 4; ks++) {
            const int kk = ks * 8;
            unsigned af[4][4];
#pragma unroll
            for (int mt = 0; mt < 4; mt++) {
                const int r0 = wm + mt * 16 + g;
                af[mt][0] = As[r0 * GP + kk + c];
                af[mt][1] = As[(r0 + 8) * GP + kk + c];
                af[mt][2] = As[r0 * GP + kk + c + 4];
                af[mt][3] = As[(r0 + 8) * GP + kk + c + 4];
            }
            unsigned bf[4][2];
#pragma unroll
            for (int nt = 0; nt < 4; nt++) {
                const int n0 = wn + nt * 8 + g;
                bf[nt][0] = Bs[n0 * GP + kk + c];
                bf[nt][1] = Bs[n0 * GP + kk + c + 4];
            }
#pragma unroll
            for (int mt = 0; mt < 4; mt++)
#pragma unroll
                for (int nt = 0; nt < 4; nt++)
                    mma_tf32(acc[mt][nt], af[mt][0], af[mt][1], af[mt][2], af[mt][3],
                             bf[nt][0], bf[nt][1]);
        }
        __syncthreads();
    }

#pragma unroll
    for (int mt = 0; mt < 4; mt++) {
        const int r0 = bm + wm + mt * 16 + g;
#pragma unroll
        for (int nt = 0; nt < 4; nt++) {
            const int c0 = bn + wn + nt * 8 + 2 * c;
            *(float2*)(Cm + (size_t)r0 * N + c0) = make_float2(acc[mt][nt][0], acc[mt][nt][1]);
            *(float2*)(Cm + (size_t)(r0 + 8) * N + c0) = make_float2(acc[mt][nt][2], acc[mt][nt][3]);
        }
    }
}

// ---------------------------------------------------------------------------
// RMSNorm(q,k) + RoPE + head-split into [B,H,T,D]; outputs tf32-rounded.
// ---------------------------------------------------------------------------
__global__ void norm_rope_kernel(const float* __restrict__ qkv)
{
    const int lane = threadIdx.x;
    const int h = blockIdx.y * 4 + threadIdx.y;
    const int bt = blockIdx.x;
    const int b = bt / TT;
    const int t = bt % TT;

    const float* row = qkv + (size_t)bt * 3 * CC;
    float q0 = row[h * 64 + lane],           q1 = row[h * 64 + lane + 32];
    float k0 = row[CC + h * 64 + lane],      k1 = row[CC + h * 64 + lane + 32];
    float v0 = row[2 * CC + h * 64 + lane],  v1 = row[2 * CC + h * 64 + lane + 32];

    float qs = q0 * q0 + q1 * q1;
    float ks = k0 * k0 + k1 * k1;
#pragma unroll
    for (int w = 16; w >= 1; w >>= 1) {
        qs += __shfl_xor_sync(0xffffffffu, qs, w);
        ks += __shfl_xor_sync(0xffffffffu, ks, w);
    }
    const float eps = 1.1920929e-7f;
    float qr = rsqrtf(qs * (1.0f / 64.0f) + eps);
    float kr = rsqrtf(ks * (1.0f / 64.0f) + eps);
    q0 *= qr; q1 *= qr; k0 *= kr; k1 *= kr;

    float inv = powf(10000.0f, -(float)lane * (1.0f / 32.0f));
    float ang = (float)t * inv;
    float sn, cs;
    sincosf(ang, &sn, &cs);

    float qo0 = q0 * cs - q1 * sn;
    float qo1 = q1 * cs + q0 * sn;
    float ko0 = k0 * cs - k1 * sn;
    float ko1 = k1 * cs + k0 * sn;

    size_t o = (((size_t)b * HH + h) * TT + t) * DD;
    g_q[o + lane] = tf32f(qo0); g_q[o + lane + 32] = tf32f(qo1);
    g_k[o + lane] = tf32f(ko0); g_k[o + lane + 32] = tf32f(ko1);
    g_v[o + lane] = tf32f(v0);  g_v[o + lane + 32] = tf32f(v1);
}

// ---------------------------------------------------------------------------
// Causal flash attention v2, tf32 mma.
// 256 threads (8 warps), 128 q-rows/block, 64-key tiles, cp.async double-buffer.
// K stored raw [key][d] pitch 68  -> S B-frags conflict-free, no transpose.
// V stored raw [key][d] pitch 72  -> PV B-frags conflict-free.
// Ps [128][68]: Q staging, then per-warp P scratch (warp w owns rows 16w..16w+15).
// ---------------------------------------------------------------------------
#define FKP 68
#define FVP 72
#define FLASH2_SMEM_BYTES ((128 * FKP + 2 * 64 * FKP + 2 * 64 * FVP) * 4)

__global__ __launch_bounds__(256, 2) void flash_mma2()
{
    extern __shared__ __align__(16) float smem[];
    float* Ps  = smem;                       // [128][FKP]
    float* KsB = smem + 128 * FKP;           // [2][64][FKP]
    float* VsB = KsB + 2 * 64 * FKP;         // [2][64][FVP]

    const int tid  = threadIdx.x;
    const int warp = tid >> 5;
    const int lane = tid & 31;
    const int g = lane >> 2;
    const int c = lane & 3;
    const int qr = warp * 16;

    const int qt = blockIdx.x;
    const int bh = blockIdx.y;
    const int qbase = qt * 128;

    const float* Q = g_q + (size_t)bh * TT * DD;
    const float* K = g_k + (size_t)bh * TT * DD;
    const float* V = g_v + (size_t)bh * TT * DD;

    // Stage Q tile [128][64] into Ps
#pragma unroll
    for (int i = 0; i < 8; i++) {
        int idx = tid + i * 256;
        int r = idx >> 4, dv = (idx & 15) * 4;
        *(float4*)&Ps[r * FKP + dv] = *(const float4*)(Q + (size_t)(qbase + r) * 64 + dv);
    }

    const uint32_t ks_s = (uint32_t)__cvta_generic_to_shared(KsB);
    const uint32_t vs_s = (uint32_t)__cvta_generic_to_shared(VsB);

    // Prefetch K/V tile 0 into buffer 0
#pragma unroll
    for (int i = 0; i < 4; i++) {
        int idx = tid + i * 256;
        int r = idx >> 4, c4 = (idx & 15) * 4;
        cp16(ks_s + (uint32_t)(r * FKP + c4) * 4, K + (size_t)r * 64 + c4);
        cp16(vs_s + (uint32_t)(r * FVP + c4) * 4, V + (size_t)r * 64 + c4);
    }
    asm volatile("cp.async.commit_group;\n");
    __syncthreads();

    // Extract Q A-fragments (per-warp rows)
    unsigned qf[8][4];
#pragma unroll
    for (int ks = 0; ks < 8; ks++) {
        const int kk = ks * 8;
        qf[ks][0] = __float_as_uint(Ps[(qr + g) * FKP + kk + c]);
        qf[ks][1] = __float_as_uint(Ps[(qr + g + 8) * FKP + kk + c]);
        qf[ks][2] = __float_as_uint(Ps[(qr + g) * FKP + kk + c + 4]);
        qf[ks][3] = __float_as_uint(Ps[(qr + g + 8) * FKP + kk + c + 4]);
    }

    float oacc[8][4];
#pragma unroll
    for (int nt = 0; nt < 8; nt++)
#pragma unroll
        for (int r = 0; r < 4; r++) oacc[nt][r] = 0.0f;
    float m0 = -1e30f, m1 = -1e30f, l0 = 0.0f, l1 = 0.0f;

    const int nkt = 2 * qt + 2;
    const int ktmax_w = 2 * qt + (warp >= 4 ? 1 : 0);
    const int q0i = qbase + qr + g;       // absolute q of row-group g
    const int q1i = q0i + 8;              // absolute q of row-group g+8

    for (int kt = 0; kt < nkt; kt++) {
        asm volatile("cp.async.wait_group 0;\n" ::: "memory");
        __syncthreads();   // buf (kt&1) ready; all warps done with buf ((kt+1)&1)

        if (kt + 1 < nkt) {
            const int kb = (kt + 1) * 64;
            const uint32_t bo = (uint32_t)(((kt + 1) & 1) * 64);
#pragma unroll
            for (int i = 0; i < 4; i++) {
                int idx = tid + i * 256;
                int r = idx >> 4, c4 = (idx & 15) * 4;
                cp16(ks_s + ((bo + r) * FKP + c4) * 4, K + (size_t)(kb + r) * 64 + c4);
                cp16(vs_s + ((bo + r) * FVP + c4) * 4, V + (size_t)(kb + r) * 64 + c4);
            }
            asm volatile("cp.async.commit_group;\n");
        }

        if (kt > ktmax_w) continue;   // fully-masked sub-tile for warps 0-3

        const float* Ks = KsB + (kt & 1) * 64 * FKP;
        const float* Vs = VsB + (kt & 1) * 64 * FVP;

        // S = Q K^T
        float sacc[8][4];
#pragma unroll
        for (int nt = 0; nt < 8; nt++)
#pragma unroll
            for (int r = 0; r < 4; r++) sacc[nt][r] = 0.0f;

#pragma unroll
        for (int ks = 0; ks < 8; ks++) {
            const int kk = ks * 8;
#pragma unroll
            for (int nt = 0; nt < 8; nt++) {
                unsigned b0 = __float_as_uint(Ks[(nt * 8 + g) * FKP + kk + c]);
                unsigned b1 = __float_as_uint(Ks[(nt * 8 + g) * FKP + kk + c + 4]);
                mma_tf32(sacc[nt], qf[ks][0], qf[ks][1], qf[ks][2], qf[ks][3], b0, b1);
            }
        }

        // scale + causal mask (only possible on the last two sub-tiles)
        const bool diag = (kt >= 2 * qt);
#pragma unroll
        for (int nt = 0; nt < 8; nt++) {
#pragma unroll
            for (int r = 0; r < 4; r++) sacc[nt][r] *= 0.125f;
            if (diag) {
                const int key0 = kt * 64 + nt * 8 + 2 * c;
                if (key0 > q0i)     sacc[nt][0] = -1e30f;
                if (key0 + 1 > q0i) sacc[nt][1] = -1e30f;
                if (key0 > q1i)     sacc[nt][2] = -1e30f;
                if (key0 + 1 > q1i) sacc[nt][3] = -1e30f;
            }
        }

        // online softmax (quad reduction over lanes sharing a row)
        float t0 = -1e30f, t1 = -1e30f;
#pragma unroll
        for (int nt = 0; nt < 8; nt++) {
            t0 = fmaxf(t0, fmaxf(sacc[nt][0], sacc[nt][1]));
            t1 = fmaxf(t1, fmaxf(sacc[nt][2], sacc[nt][3]));
        }
#pragma unroll
        for (int w = 1; w <= 2; w <<= 1) {
            t0 = fmaxf(t0, __shfl_xor_sync(0xffffffffu, t0, w));
            t1 = fmaxf(t1, __shfl_xor_sync(0xffffffffu, t1, w));
        }
        float mn0 = fmaxf(m0, t0), mn1 = fmaxf(m1, t1);
        float al0 = __expf(m0 - mn0), al1 = __expf(m1 - mn1);
        m0 = mn0; m1 = mn1;

        float rs0 = 0.0f, rs1 = 0.0f;
        __syncwarp();   // prior PV A-frag reads of Ps done (warp-private rows)
#pragma unroll
        for (int nt = 0; nt < 8; nt++) {
            float p0 = __expf(sacc[nt][0] - m0);
            float p1 = __expf(sacc[nt][1] - m0);
            float p2 = __expf(sacc[nt][2] - m1);
            float p3 = __expf(sacc[nt][3] - m1);
            rs0 += p0 + p1; rs1 += p2 + p3;
            const int col = nt * 8 + 2 * c;
            *(float2*)&Ps[(qr + g) * FKP + col]     = make_float2(tf32f(p0), tf32f(p1));
            *(float2*)&Ps[(qr + g + 8) * FKP + col] = make_float2(tf32f(p2), tf32f(p3));
        }
#pragma unroll
        for (int w = 1; w <= 2; w <<= 1) {
            rs0 += __shfl_xor_sync(0xffffffffu, rs0, w);
            rs1 += __shfl_xor_sync(0xffffffffu, rs1, w);
        }
        l0 = l0 * al0 + rs0;
        l1 = l1 * al1 + rs1;
#pragma unroll
        for (int nt = 0; nt < 8; nt++) {
            oacc[nt][0] *= al0; oacc[nt][1] *= al0;
            oacc[nt][2] *= al1; oacc[nt][3] *= al1;
        }
        __syncwarp();   // P visible to whole warp

        // O += P V
#pragma unroll
        for (int ks = 0; ks < 8; ks++) {
            const int kk = ks * 8;
            unsigned pf0 = __float_as_uint(Ps[(qr + g) * FKP + kk + c]);
            unsigned pf1 = __float_as_uint(Ps[(qr + g + 8) * FKP + kk + c]);
            unsigned pf2 = __float_as_uint(Ps[(qr + g) * FKP + kk + c + 4]);
            unsigned pf3 = __float_as_uint(Ps[(qr + g + 8) * FKP + kk + c + 4]);
#pragma unroll
            for (int nt = 0; nt < 8; nt++) {
                unsigned b0 = __float_as_uint(Vs[(kk + c) * FVP + nt * 8 + g]);
                unsigned b1 = __float_as_uint(Vs[(kk + c + 4) * FVP + nt * 8 + g]);
                mma_tf32(oacc[nt], pf0, pf1, pf2, pf3, b0, b1);
            }
        }
    }

    // Epilogue: normalize, scatter heads back into [B,T,C]
    const int b = bh / HH;
    const int h = bh % HH;
    const float inv0 = 1.0f / l0, inv1 = 1.0f / l1;
    const int row0 = qbase + qr + g;
#pragma unroll
    for (int nt = 0; nt < 8; nt++) {
        const int col = h * 64 + nt * 8 + 2 * c;
        *(float2*)(g_y + (size_t)(b * TT + row0) * CC + col) =
            make_float2(oacc[nt][0] * inv0, oacc[nt][1] * inv0);
        *(float2*)(g_y + (size_t)(b * TT + row0 + 8) * CC + col) =
            make_float2(oacc[nt][2] * inv1, oacc[nt][3] * inv1);
    }
}

// ---------------------------------------------------------------------------
extern "C" void kernel_launch(void* const* d_in, const int* in_sizes, int n_in,
                              void* d_out, int out_size)
{
    const float* x      = (const float*)d_in[0];
    const float* w_attn = (const float*)d_in[1];
    const float* w_proj = (const float*)d_in[2];
    float* out = (float*)d_out;

    float *qkv, *y;
    cudaGetSymbolAddress((void**)&qkv, g_qkv);
    cudaGetSymbolAddress((void**)&y, g_y);

    // 1) QKV projection
    mma_gemm_abt<<<dim3(3 * CC / 128, BB * TT / 128), 256>>>(x, w_attn, qkv,
                                                             BB * TT, 3 * CC, CC);
    // 2) RMSNorm + RoPE + head split (tf32-rounded outputs)
    norm_rope_kernel<<<dim3(BB * TT, HH / 4), dim3(32, 4)>>>(qkv);

    // 3) Causal flash attention v2
    cudaFuncSetAttribute(flash_mma2, cudaFuncAttributeMaxDynamicSharedMemorySize,
                         FLASH2_SMEM_BYTES);
    flash_mma2<<<dim3(TT / 128, BB * HH), 256, FLASH2_SMEM_BYTES>>>();

    // 4) Output projection
    mma_gemm_abt<<<dim3(CC / 128, BB * TT / 128), 256>>>(y, w_proj, out,
                                                         BB * TT, CC, CC);
}

// round 5
// speedup vs baseline: 1.6604x; 1.6604x over previous
#include <cuda_runtime.h>
#include <math.h>
#include <stdint.h>

// Problem constants
#define BB 2
#define TT 2048
#define HH 16
#define DD 64
#define CC 1024

// Scratch (device globals: allocation-free per harness rules)
__device__ float g_qkv[BB * TT * 3 * CC];
__device__ float g_q[BB * HH * TT * DD];
__device__ float g_k[BB * HH * TT * DD];
__device__ float g_v[BB * HH * TT * DD];
__device__ float g_y[BB * TT * CC];

// ---------------------------------------------------------------------------
// tf32 / async helpers
// ---------------------------------------------------------------------------
__device__ __forceinline__ unsigned tf32u(float x) {
    unsigned u;
    asm("cvt.rna.tf32.f32 %0, %1;" : "=r"(u) : "f"(x));
    return u;
}
__device__ __forceinline__ float tf32f(float x) {
    return __uint_as_float(tf32u(x));
}

__device__ __forceinline__ void mma_tf32(float* d,
    unsigned a0, unsigned a1, unsigned a2, unsigned a3,
    unsigned b0, unsigned b1)
{
    asm volatile(
        "mma.sync.aligned.m16n8k8.row.col.f32.tf32.tf32.f32 "
        "{%0,%1,%2,%3}, {%4,%5,%6,%7}, {%8,%9}, {%0,%1,%2,%3};\n"
        : "+f"(d[0]), "+f"(d[1]), "+f"(d[2]), "+f"(d[3])
        : "r"(a0), "r"(a1), "r"(a2), "r"(a3), "r"(b0), "r"(b1));
}

__device__ __forceinline__ void cp16(uint32_t s, const void* g) {
    asm volatile("cp.async.cg.shared.global [%0], [%1], 16;\n" :: "r"(s), "l"(g));
}
__device__ __forceinline__ void cp_commit() {
    asm volatile("cp.async.commit_group;\n");
}
__device__ __forceinline__ void cp_wait0() {
    asm volatile("cp.async.wait_group 0;\n" ::: "memory");
}

// ---------------------------------------------------------------------------
// tf32 tensor-core GEMM: C[m][n] = sum_k A[m][k] * B[n][k]  (C = A * B^T)
// 128x128 block tile, BK=32, 256 threads (8 warps), warp tile 64x32.
// cp.async double-buffered; raw fp32 in smem, RNA tf32 cvt after fragment LDS.
// ---------------------------------------------------------------------------
#define GP 36

__global__ __launch_bounds__(256) void mma_gemm_abt(
    const float* __restrict__ A, const float* __restrict__ Bm,
    float* __restrict__ Cm, int M, int N, int K)
{
    __shared__ __align__(16) float As[2][128 * GP];
    __shared__ __align__(16) float Bs[2][128 * GP];

    const int tid  = threadIdx.x;
    const int warp = tid >> 5;
    const int lane = tid & 31;
    const int g = lane >> 2;
    const int c = lane & 3;

    const int wm = (warp & 1) * 64;
    const int wn = (warp >> 1) * 32;

    const int bm = blockIdx.y * 128;
    const int bn = blockIdx.x * 128;

    const int lrow = tid >> 3;         // 0..31
    const int lcol = (tid & 7) * 4;    // 0..28

    const uint32_t as_s = (uint32_t)__cvta_generic_to_shared(As);
    const uint32_t bs_s = (uint32_t)__cvta_generic_to_shared(Bs);
    const uint32_t bufB = 128 * GP * 4;   // bytes per buffer

    // Prefetch k-tile 0 into buffer 0
#pragma unroll
    for (int i = 0; i < 4; i++) {
        const uint32_t so = (uint32_t)((lrow + i * 32) * GP + lcol) * 4;
        cp16(as_s + so, A + (size_t)(bm + lrow + i * 32) * K + lcol);
        cp16(bs_s + so, Bm + (size_t)(bn + lrow + i * 32) * K + lcol);
    }
    cp_commit();

    float acc[4][4][4];
#pragma unroll
    for (int i = 0; i < 4; i++)
#pragma unroll
        for (int j = 0; j < 4; j++)
#pragma unroll
            for (int r = 0; r < 4; r++) acc[i][j][r] = 0.0f;

    int buf = 0;
    for (int k0 = 0; k0 < K; k0 += 32, buf ^= 1) {
        cp_wait0();
        __syncthreads();   // buf data ready; all warps done reading buf^1

        if (k0 + 32 < K) {
            const uint32_t bo = (buf ^ 1) * bufB;
#pragma unroll
            for (int i = 0; i < 4; i++) {
                const uint32_t so = bo + (uint32_t)((lrow + i * 32) * GP + lcol) * 4;
                cp16(as_s + so, A + (size_t)(bm + lrow + i * 32) * K + k0 + 32 + lcol);
                cp16(bs_s + so, Bm + (size_t)(bn + lrow + i * 32) * K + k0 + 32 + lcol);
            }
            cp_commit();
        }

        const float* Ac = As[buf];
        const float* Bc = Bs[buf];
#pragma unroll
        for (int ks = 0; ks < 4; ks++) {
            const int kk = ks * 8;
            unsigned af[4][4];
#pragma unroll
            for (int mt = 0; mt < 4; mt++) {
                const int r0 = wm + mt * 16 + g;
                af[mt][0] = tf32u(Ac[r0 * GP + kk + c]);
                af[mt][1] = tf32u(Ac[(r0 + 8) * GP + kk + c]);
                af[mt][2] = tf32u(Ac[r0 * GP + kk + c + 4]);
                af[mt][3] = tf32u(Ac[(r0 + 8) * GP + kk + c + 4]);
            }
            unsigned bf[4][2];
#pragma unroll
            for (int nt = 0; nt < 4; nt++) {
                const int n0 = wn + nt * 8 + g;
                bf[nt][0] = tf32u(Bc[n0 * GP + kk + c]);
                bf[nt][1] = tf32u(Bc[n0 * GP + kk + c + 4]);
            }
#pragma unroll
            for (int mt = 0; mt < 4; mt++)
#pragma unroll
                for (int nt = 0; nt < 4; nt++)
                    mma_tf32(acc[mt][nt], af[mt][0], af[mt][1], af[mt][2], af[mt][3],
                             bf[nt][0], bf[nt][1]);
        }
    }

#pragma unroll
    for (int mt = 0; mt < 4; mt++) {
        const int r0 = bm + wm + mt * 16 + g;
#pragma unroll
        for (int nt = 0; nt < 4; nt++) {
            const int c0 = bn + wn + nt * 8 + 2 * c;
            *(float2*)(Cm + (size_t)r0 * N + c0) = make_float2(acc[mt][nt][0], acc[mt][nt][1]);
            *(float2*)(Cm + (size_t)(r0 + 8) * N + c0) = make_float2(acc[mt][nt][2], acc[mt][nt][3]);
        }
    }
}

// ---------------------------------------------------------------------------
// RMSNorm(q,k) + RoPE + head-split into [B,H,T,D]; outputs tf32-rounded.
// ---------------------------------------------------------------------------
__global__ void norm_rope_kernel(const float* __restrict__ qkv)
{
    const int lane = threadIdx.x;
    const int h = blockIdx.y * 4 + threadIdx.y;
    const int bt = blockIdx.x;
    const int b = bt / TT;
    const int t = bt % TT;

    const float* row = qkv + (size_t)bt * 3 * CC;
    float q0 = row[h * 64 + lane],           q1 = row[h * 64 + lane + 32];
    float k0 = row[CC + h * 64 + lane],      k1 = row[CC + h * 64 + lane + 32];
    float v0 = row[2 * CC + h * 64 + lane],  v1 = row[2 * CC + h * 64 + lane + 32];

    float qs = q0 * q0 + q1 * q1;
    float ks = k0 * k0 + k1 * k1;
#pragma unroll
    for (int w = 16; w >= 1; w >>= 1) {
        qs += __shfl_xor_sync(0xffffffffu, qs, w);
        ks += __shfl_xor_sync(0xffffffffu, ks, w);
    }
    const float eps = 1.1920929e-7f;
    float qr = rsqrtf(qs * (1.0f / 64.0f) + eps);
    float kr = rsqrtf(ks * (1.0f / 64.0f) + eps);
    q0 *= qr; q1 *= qr; k0 *= kr; k1 *= kr;

    float inv = powf(10000.0f, -(float)lane * (1.0f / 32.0f));
    float ang = (float)t * inv;
    float sn, cs;
    sincosf(ang, &sn, &cs);

    float qo0 = q0 * cs - q1 * sn;
    float qo1 = q1 * cs + q0 * sn;
    float ko0 = k0 * cs - k1 * sn;
    float ko1 = k1 * cs + k0 * sn;

    size_t o = (((size_t)b * HH + h) * TT + t) * DD;
    g_q[o + lane] = tf32f(qo0); g_q[o + lane + 32] = tf32f(qo1);
    g_k[o + lane] = tf32f(ko0); g_k[o + lane + 32] = tf32f(ko1);
    g_v[o + lane] = tf32f(v0);  g_v[o + lane + 32] = tf32f(v1);
}

// ---------------------------------------------------------------------------
// Causal flash attention, tf32 mma.
// 256 threads (8 warps), 128 q-rows/block, 64-key tiles, cp.async double-buffer.
// K raw [key][d] pitch 68 -> S B-frags conflict-free (no transpose).
// V raw [key][d] pitch 72 -> PV B-frags conflict-free.
// Ps [128][68]: Q staging, then per-warp P scratch.
// NO min-blocks clamp: let the compiler take ~160 regs (R4's ",2" forced spills).
// ---------------------------------------------------------------------------
#define FKP 68
#define FVP 72
#define FLASH2_SMEM_BYTES ((128 * FKP + 2 * 64 * FKP + 2 * 64 * FVP) * 4)

__global__ __launch_bounds__(256) void flash_mma2()
{
    extern __shared__ __align__(16) float smem[];
    float* Ps  = smem;                       // [128][FKP]
    float* KsB = smem + 128 * FKP;           // [2][64][FKP]
    float* VsB = KsB + 2 * 64 * FKP;         // [2][64][FVP]

    const int tid  = threadIdx.x;
    const int warp = tid >> 5;
    const int lane = tid & 31;
    const int g = lane >> 2;
    const int c = lane & 3;
    const int qr = warp * 16;

    const int qt = gridDim.x - 1 - blockIdx.x;   // heavy tiles first
    const int bh = blockIdx.y;
    const int qbase = qt * 128;

    const float* Q = g_q + (size_t)bh * TT * DD;
    const float* K = g_k + (size_t)bh * TT * DD;
    const float* V = g_v + (size_t)bh * TT * DD;

    // Stage Q tile [128][64] into Ps
#pragma unroll
    for (int i = 0; i < 8; i++) {
        int idx = tid + i * 256;
        int r = idx >> 4, dv = (idx & 15) * 4;
        *(float4*)&Ps[r * FKP + dv] = *(const float4*)(Q + (size_t)(qbase + r) * 64 + dv);
    }

    const uint32_t ks_s = (uint32_t)__cvta_generic_to_shared(KsB);
    const uint32_t vs_s = (uint32_t)__cvta_generic_to_shared(VsB);

    // Prefetch K/V tile 0 into buffer 0
#pragma unroll
    for (int i = 0; i < 4; i++) {
        int idx = tid + i * 256;
        int r = idx >> 4, c4 = (idx & 15) * 4;
        cp16(ks_s + (uint32_t)(r * FKP + c4) * 4, K + (size_t)r * 64 + c4);
        cp16(vs_s + (uint32_t)(r * FVP + c4) * 4, V + (size_t)r * 64 + c4);
    }
    cp_commit();
    __syncthreads();

    // Extract Q A-fragments (per-warp rows)
    unsigned qf[8][4];
#pragma unroll
    for (int ks = 0; ks < 8; ks++) {
        const int kk = ks * 8;
        qf[ks][0] = __float_as_uint(Ps[(qr + g) * FKP + kk + c]);
        qf[ks][1] = __float_as_uint(Ps[(qr + g + 8) * FKP + kk + c]);
        qf[ks][2] = __float_as_uint(Ps[(qr + g) * FKP + kk + c + 4]);
        qf[ks][3] = __float_as_uint(Ps[(qr + g + 8) * FKP + kk + c + 4]);
    }

    float oacc[8][4];
#pragma unroll
    for (int nt = 0; nt < 8; nt++)
#pragma unroll
        for (int r = 0; r < 4; r++) oacc[nt][r] = 0.0f;
    float m0 = -1e30f, m1 = -1e30f, l0 = 0.0f, l1 = 0.0f;

    const int nkt = 2 * qt + 2;
    const int ktmax_w = 2 * qt + (warp >= 4 ? 1 : 0);
    const int q0i = qbase + qr + g;
    const int q1i = q0i + 8;

    for (int kt = 0; kt < nkt; kt++) {
        cp_wait0();
        __syncthreads();   // buf (kt&1) ready; all warps done with buf ((kt+1)&1)

        if (kt + 1 < nkt) {
            const int kb = (kt + 1) * 64;
            const uint32_t bo = (uint32_t)(((kt + 1) & 1) * 64);
#pragma unroll
            for (int i = 0; i < 4; i++) {
                int idx = tid + i * 256;
                int r = idx >> 4, c4 = (idx & 15) * 4;
                cp16(ks_s + ((bo + r) * FKP + c4) * 4, K + (size_t)(kb + r) * 64 + c4);
                cp16(vs_s + ((bo + r) * FVP + c4) * 4, V + (size_t)(kb + r) * 64 + c4);
            }
            cp_commit();
        }

        if (kt > ktmax_w) continue;   // fully-masked sub-tile

        const float* Ks = KsB + (kt & 1) * 64 * FKP;
        const float* Vs = VsB + (kt & 1) * 64 * FVP;

        // S = Q K^T
        float sacc[8][4];
#pragma unroll
        for (int nt = 0; nt < 8; nt++)
#pragma unroll
            for (int r = 0; r < 4; r++) sacc[nt][r] = 0.0f;

#pragma unroll
        for (int ks = 0; ks < 8; ks++) {
            const int kk = ks * 8;
#pragma unroll
            for (int nt = 0; nt < 8; nt++) {
                unsigned b0 = __float_as_uint(Ks[(nt * 8 + g) * FKP + kk + c]);
                unsigned b1 = __float_as_uint(Ks[(nt * 8 + g) * FKP + kk + c + 4]);
                mma_tf32(sacc[nt], qf[ks][0], qf[ks][1], qf[ks][2], qf[ks][3], b0, b1);
            }
        }

        // scale + causal mask
        const bool diag = (kt >= 2 * qt);
#pragma unroll
        for (int nt = 0; nt < 8; nt++) {
#pragma unroll
            for (int r = 0; r < 4; r++) sacc[nt][r] *= 0.125f;
            if (diag) {
                const int key0 = kt * 64 + nt * 8 + 2 * c;
                if (key0 > q0i)     sacc[nt][0] = -1e30f;
                if (key0 + 1 > q0i) sacc[nt][1] = -1e30f;
                if (key0 > q1i)     sacc[nt][2] = -1e30f;
                if (key0 + 1 > q1i) sacc[nt][3] = -1e30f;
            }
        }

        // online softmax
        float t0 = -1e30f, t1 = -1e30f;
#pragma unroll
        for (int nt = 0; nt < 8; nt++) {
            t0 = fmaxf(t0, fmaxf(sacc[nt][0], sacc[nt][1]));
            t1 = fmaxf(t1, fmaxf(sacc[nt][2], sacc[nt][3]));
        }
#pragma unroll
        for (int w = 1; w <= 2; w <<= 1) {
            t0 = fmaxf(t0, __shfl_xor_sync(0xffffffffu, t0, w));
            t1 = fmaxf(t1, __shfl_xor_sync(0xffffffffu, t1, w));
        }
        float mn0 = fmaxf(m0, t0), mn1 = fmaxf(m1, t1);
        float al0 = __expf(m0 - mn0), al1 = __expf(m1 - mn1);
        m0 = mn0; m1 = mn1;

        float rs0 = 0.0f, rs1 = 0.0f;
        __syncwarp();   // prior PV A-frag reads of Ps done (warp-private rows)
#pragma unroll
        for (int nt = 0; nt < 8; nt++) {
            float p0 = __expf(sacc[nt][0] - m0);
            float p1 = __expf(sacc[nt][1] - m0);
            float p2 = __expf(sacc[nt][2] - m1);
            float p3 = __expf(sacc[nt][3] - m1);
            rs0 += p0 + p1; rs1 += p2 + p3;
            const int col = nt * 8 + 2 * c;
            *(float2*)&Ps[(qr + g) * FKP + col]     = make_float2(tf32f(p0), tf32f(p1));
            *(float2*)&Ps[(qr + g + 8) * FKP + col] = make_float2(tf32f(p2), tf32f(p3));
        }
#pragma unroll
        for (int w = 1; w <= 2; w <<= 1) {
            rs0 += __shfl_xor_sync(0xffffffffu, rs0, w);
            rs1 += __shfl_xor_sync(0xffffffffu, rs1, w);
        }
        l0 = l0 * al0 + rs0;
        l1 = l1 * al1 + rs1;
#pragma unroll
        for (int nt = 0; nt < 8; nt++) {
            oacc[nt][0] *= al0; oacc[nt][1] *= al0;
            oacc[nt][2] *= al1; oacc[nt][3] *= al1;
        }
        __syncwarp();   // P visible to whole warp

        // O += P V
#pragma unroll
        for (int ks = 0; ks < 8; ks++) {
            const int kk = ks * 8;
            unsigned pf0 = __float_as_uint(Ps[(qr + g) * FKP + kk + c]);
            unsigned pf1 = __float_as_uint(Ps[(qr + g + 8) * FKP + kk + c]);
            unsigned pf2 = __float_as_uint(Ps[(qr + g) * FKP + kk + c + 4]);
            unsigned pf3 = __float_as_uint(Ps[(qr + g + 8) * FKP + kk + c + 4]);
#pragma unroll
            for (int nt = 0; nt < 8; nt++) {
                unsigned b0 = __float_as_uint(Vs[(kk + c) * FVP + nt * 8 + g]);
                unsigned b1 = __float_as_uint(Vs[(kk + c + 4) * FVP + nt * 8 + g]);
                mma_tf32(oacc[nt], pf0, pf1, pf2, pf3, b0, b1);
            }
        }
    }

    // Epilogue: normalize, scatter heads back into [B,T,C]
    const int b = bh / HH;
    const int h = bh % HH;
    const float inv0 = 1.0f / l0, inv1 = 1.0f / l1;
    const int row0 = qbase + qr + g;
#pragma unroll
    for (int nt = 0; nt < 8; nt++) {
        const int col = h * 64 + nt * 8 + 2 * c;
        *(float2*)(g_y + (size_t)(b * TT + row0) * CC + col) =
            make_float2(oacc[nt][0] * inv0, oacc[nt][1] * inv0);
        *(float2*)(g_y + (size_t)(b * TT + row0 + 8) * CC + col) =
            make_float2(oacc[nt][2] * inv1, oacc[nt][3] * inv1);
    }
}

// ---------------------------------------------------------------------------
extern "C" void kernel_launch(void* const* d_in, const int* in_sizes, int n_in,
                              void* d_out, int out_size)
{
    const float* x      = (const float*)d_in[0];
    const float* w_attn = (const float*)d_in[1];
    const float* w_proj = (const float*)d_in[2];
    float* out = (float*)d_out;

    float *qkv, *y;
    cudaGetSymbolAddress((void**)&qkv, g_qkv);
    cudaGetSymbolAddress((void**)&y, g_y);

    // 1) QKV projection
    mma_gemm_abt<<<dim3(3 * CC / 128, BB * TT / 128), 256>>>(x, w_attn, qkv,
                                                             BB * TT, 3 * CC, CC);
    // 2) RMSNorm + RoPE + head split (tf32-rounded outputs)
    norm_rope_kernel<<<dim3(BB * TT, HH / 4), dim3(32, 4)>>>(qkv);

    // 3) Causal flash attention
    cudaFuncSetAttribute(flash_mma2, cudaFuncAttributeMaxDynamicSharedMemorySize,
                         FLASH2_SMEM_BYTES);
    flash_mma2<<<dim3(TT / 128, BB * HH), 256, FLASH2_SMEM_BYTES>>>();

    // 4) Output projection
    mma_gemm_abt<<<dim3(CC / 128, BB * TT / 128), 256>>>(y, w_proj, out,
                                                         BB * TT, CC, CC);
}